// round 14
// baseline (speedup 1.0000x reference)
#include <cuda_runtime.h>
#include <cstdint>

#define NS 4
#define CD 2048
#define FLT 8192
#define BR 4096
#define DFF 8192

// ---------------------------------------------------------------- scratch
__device__ float g_fin[(size_t)BR * CD];        // (B, C)    32 MB  (tf32-rounded)
__device__ float g_hidden[(size_t)BR * DFF];    // (B, DFF) 128 MB  (tf32-rounded)
__device__ float g_hpre[BR * NS];               // (B, 4) sigmoid gates
__device__ float g_hpost[BR * NS];              // (B, 4)
__device__ float g_hres[BR * NS * NS];          // (B, 4, 4)

// ---------------------------------------------------------------- helpers
__device__ __forceinline__ float fast_tanhf(float u) {
    float e = __expf(2.0f * u);
    return 1.0f - __fdividef(2.0f, e + 1.0f);
}
__device__ __forceinline__ float gelu_tanh(float x) {
    float u = 0.7978845608028654f * fmaf(0.044715f * x, x * x, x);
    return 0.5f * x * (1.0f + fast_tanhf(u));
}
__device__ __forceinline__ uint32_t f2tf32(float x) {
    uint32_t u;
    asm("cvt.rna.tf32.f32 %0, %1;" : "=r"(u) : "f"(x));
    return u;
}
__device__ __forceinline__ float roundtf(float x) { return __uint_as_float(f2tf32(x)); }
__device__ __forceinline__ uint32_t smem_u32(const void* p) {
    uint32_t a;
    asm("{ .reg .u64 t; cvta.to.shared.u64 t, %1; cvt.u32.u64 %0, t; }" : "=r"(a) : "l"(p));
    return a;
}
__device__ __forceinline__ void cp16(uint32_t dst, const void* src) {
    asm volatile("cp.async.cg.shared.global [%0], [%1], 16;" :: "r"(dst), "l"(src));
}
__device__ __forceinline__ void cp_commit() {
    asm volatile("cp.async.commit_group;" ::: "memory");
}
template <int N>
__device__ __forceinline__ void cp_wait() {
    asm volatile("cp.async.wait_group %0;" :: "n"(N) : "memory");
}

// ---------------------------------------------------------------- dots (4 rows/block, 128 thr, high occ)
#define DROWS 4
__global__ __launch_bounds__(128, 3) void dots_kernel(
    const float* __restrict__ x,
    const float* __restrict__ phi_pre,
    const float* __restrict__ phi_post,
    const float* __restrict__ phi_res,
    const float* __restrict__ bias_pre,
    const float* __restrict__ bias_post,
    const float* __restrict__ bias_res,
    const float* __restrict__ alpha_pre_p,
    const float* __restrict__ alpha_post_p,
    const float* __restrict__ alpha_res_p)
{
    __shared__ float sred[4][DROWS * 25];
    __shared__ float sdot[DROWS * 25];

    const int tid = threadIdx.x;
    const int b0 = blockIdx.x * DROWS;
    const float* xb = x + (size_t)b0 * FLT;

    float acc[DROWS * 25];
    #pragma unroll
    for (int j = 0; j < DROWS * 25; j++) acc[j] = 0.0f;

    const float4* pp4 = (const float4*)phi_pre;
    const float4* pq4 = (const float4*)phi_post;
    const float4* pr4 = (const float4*)phi_res;

    #pragma unroll 2
    for (int it = 0; it < FLT / 128; it++) {
        const int f = tid + it * 128;
        float xv[DROWS];
        #pragma unroll
        for (int r = 0; r < DROWS; r++) {
            xv[r] = xb[r * FLT + f];
            acc[r * 25 + 24] = fmaf(xv[r], xv[r], acc[r * 25 + 24]);
        }
        float4 p = pp4[f];
        #pragma unroll
        for (int r = 0; r < DROWS; r++) {
            acc[r*25 + 0] = fmaf(xv[r], p.x, acc[r*25 + 0]);
            acc[r*25 + 1] = fmaf(xv[r], p.y, acc[r*25 + 1]);
            acc[r*25 + 2] = fmaf(xv[r], p.z, acc[r*25 + 2]);
            acc[r*25 + 3] = fmaf(xv[r], p.w, acc[r*25 + 3]);
        }
        float4 q = pq4[f];
        #pragma unroll
        for (int r = 0; r < DROWS; r++) {
            acc[r*25 + 4] = fmaf(xv[r], q.x, acc[r*25 + 4]);
            acc[r*25 + 5] = fmaf(xv[r], q.y, acc[r*25 + 5]);
            acc[r*25 + 6] = fmaf(xv[r], q.z, acc[r*25 + 6]);
            acc[r*25 + 7] = fmaf(xv[r], q.w, acc[r*25 + 7]);
        }
        #pragma unroll
        for (int g = 0; g < 4; g++) {
            float4 rr = pr4[f * 4 + g];
            #pragma unroll
            for (int r = 0; r < DROWS; r++) {
                acc[r*25 + 8 + g*4 + 0] = fmaf(xv[r], rr.x, acc[r*25 + 8 + g*4 + 0]);
                acc[r*25 + 8 + g*4 + 1] = fmaf(xv[r], rr.y, acc[r*25 + 8 + g*4 + 1]);
                acc[r*25 + 8 + g*4 + 2] = fmaf(xv[r], rr.z, acc[r*25 + 8 + g*4 + 2]);
                acc[r*25 + 8 + g*4 + 3] = fmaf(xv[r], rr.w, acc[r*25 + 8 + g*4 + 3]);
            }
        }
    }

    const int lane = tid & 31, warp = tid >> 5;
    #pragma unroll
    for (int j = 0; j < DROWS * 25; j++) {
        float v = acc[j];
        v += __shfl_xor_sync(0xffffffffu, v, 16);
        v += __shfl_xor_sync(0xffffffffu, v, 8);
        v += __shfl_xor_sync(0xffffffffu, v, 4);
        v += __shfl_xor_sync(0xffffffffu, v, 2);
        v += __shfl_xor_sync(0xffffffffu, v, 1);
        if (lane == 0) sred[warp][j] = v;
    }
    __syncthreads();
    if (tid < DROWS * 25) {
        sdot[tid] = sred[0][tid] + sred[1][tid] + sred[2][tid] + sred[3][tid];
    }
    __syncthreads();
    if (tid < DROWS) {
        const int rowoff = tid * 25;
        const int b = b0 + tid;
        float inv_rms = rsqrtf(sdot[rowoff + 24] * (1.0f / (float)FLT) + 1e-8f);
        float a_pre = alpha_pre_p[0], a_post = alpha_post_p[0], a_res = alpha_res_p[0];
        #pragma unroll
        for (int n = 0; n < 4; n++) {
            float tpre = fmaf(a_pre, sdot[rowoff + n] * inv_rms, bias_pre[n]);
            g_hpre[b * 4 + n] = 1.0f / (1.0f + expf(-tpre));
            float tpost = fmaf(a_post, sdot[rowoff + 4 + n] * inv_rms, bias_post[n]);
            g_hpost[b * 4 + n] = 2.0f / (1.0f + expf(-tpost));
        }
        float M[4][4];
        #pragma unroll
        for (int m = 0; m < 4; m++)
            #pragma unroll
            for (int n = 0; n < 4; n++)
                M[m][n] = expf(fmaf(a_res, sdot[rowoff + 8 + m*4 + n] * inv_rms, bias_res[m*4 + n]));
        #pragma unroll 1
        for (int it = 0; it < 20; it++) {
            #pragma unroll
            for (int m = 0; m < 4; m++) {
                float rs = M[m][0] + M[m][1] + M[m][2] + M[m][3] + 1e-12f;
                float inv = 1.0f / rs;
                M[m][0] *= inv; M[m][1] *= inv; M[m][2] *= inv; M[m][3] *= inv;
            }
            #pragma unroll
            for (int n = 0; n < 4; n++) {
                float cs = M[0][n] + M[1][n] + M[2][n] + M[3][n] + 1e-12f;
                float inv = 1.0f / cs;
                M[0][n] *= inv; M[1][n] *= inv; M[2][n] *= inv; M[3][n] *= inv;
            }
        }
        #pragma unroll
        for (int m = 0; m < 4; m++)
            #pragma unroll
            for (int n = 0; n < 4; n++)
                g_hres[b * 16 + m * 4 + n] = M[m][n];
    }
}

// ---------------------------------------------------------------- apply (1 row/block; streams x once)
__global__ __launch_bounds__(256) void apply_kernel(
    const float* __restrict__ x, float* __restrict__ out)
{
    const int b = blockIdx.x;
    const int tid = threadIdx.x;
    __shared__ float hp[4];
    __shared__ float hrm[16];
    if (tid < 4) hp[tid] = g_hpre[b * 4 + tid];
    if (tid < 16) hrm[tid] = g_hres[b * 16 + tid];
    __syncthreads();

    const float h0 = hp[0], h1 = hp[1], h2 = hp[2], h3 = hp[3];
    float R[4][4];
    #pragma unroll
    for (int m = 0; m < 4; m++)
        #pragma unroll
        for (int n = 0; n < 4; n++)
            R[m][n] = hrm[m * 4 + n];

    const float4* xb = (const float4*)(x + (size_t)b * FLT);
    float4* fin4 = (float4*)(g_fin + (size_t)b * CD);
    #pragma unroll
    for (int c = tid; c < CD / 4; c += 256) {
        float4 x0 = xb[c];
        float4 x1 = xb[512 + c];
        float4 x2 = xb[1024 + c];
        float4 x3 = xb[1536 + c];
        float4 fv;
        fv.x = roundtf(h0*x0.x + h1*x1.x + h2*x2.x + h3*x3.x);
        fv.y = roundtf(h0*x0.y + h1*x1.y + h2*x2.y + h3*x3.y);
        fv.z = roundtf(h0*x0.z + h1*x1.z + h2*x2.z + h3*x3.z);
        fv.w = roundtf(h0*x0.w + h1*x1.w + h2*x2.w + h3*x3.w);
        fin4[c] = fv;
        #pragma unroll
        for (int m = 0; m < 4; m++) {
            float4 ov;
            ov.x = R[m][0]*x0.x + R[m][1]*x1.x + R[m][2]*x2.x + R[m][3]*x3.x;
            ov.y = R[m][0]*x0.y + R[m][1]*x1.y + R[m][2]*x2.y + R[m][3]*x3.y;
            ov.z = R[m][0]*x0.z + R[m][1]*x1.z + R[m][2]*x2.z + R[m][3]*x3.z;
            ov.w = R[m][0]*x0.w + R[m][1]*x1.w + R[m][2]*x2.w + R[m][3]*x3.w;
            ((float4*)(out + ((size_t)b * 4 + m) * CD))[c] = ov;
        }
    }
}

// ---------------------------------------------------------------- tf32 GEMM
// Block tile 128x128, BK=32, 128 threads = 4 warps (2x2), warp tile 64x64.
// Single-sync multistage; rolling stage indices. B converted to tf32 in-loop
// (weights read raw from the harness's W1/W2; A pre-rounded at producers).
#define STAGES 3
#define BKK 32
#define GBM 128
#define GBN 128
#define GT 128
#define PA 36
#define PB 136
#define A_STG (GBM * PA)
#define B_STG (BKK * PB)
#define SMEM_GEMM ((STAGES * (A_STG + B_STG)) * 4)   // 107520 B

__device__ __forceinline__ void issue_chunk(
    const float* __restrict__ A, const float* __restrict__ Bm,
    int KDIM, int NDIM, int bm0, int bn0, int kt,
    uint32_t smA, uint32_t smB, int tid)
{
    #pragma unroll
    for (int q = 0; q < 8; q++) {
        int idx = q * GT + tid;
        int row = idx >> 3;
        int c4 = idx & 7;
        cp16(smA + (row * PA + c4 * 4) * 4,
             A + (size_t)(bm0 + row) * KDIM + kt + c4 * 4);
    }
    #pragma unroll
    for (int q = 0; q < 8; q++) {
        int idx = q * GT + tid;
        int row = idx >> 5;
        int c4 = idx & 31;
        cp16(smB + (row * PB + c4 * 4) * 4,
             Bm + (size_t)(kt + row) * NDIM + bn0 + c4 * 4);
    }
}

__device__ __forceinline__ void gemm_mainloop(
    const float* __restrict__ A, const float* __restrict__ Bm,
    int KDIM, int NDIM, int bm0, int bn0,
    float* sm, float acc[4][8][4])
{
    const int tid = threadIdx.x;
    const int lane = tid & 31, wid = tid >> 5;
    const int wm = wid >> 1, wn = wid & 1;
    const int gid = lane >> 2, tig = lane & 3;

    float* sA = sm;
    float* sB = sm + STAGES * A_STG;
    const uint32_t sAu = smem_u32(sA);
    const uint32_t sBu = smem_u32(sB);

    const int nch = KDIM / BKK;

    #pragma unroll
    for (int i = 0; i < STAGES - 1; i++) {
        issue_chunk(A, Bm, KDIM, NDIM, bm0, bn0, i * BKK,
                    sAu + i * A_STG * 4, sBu + i * B_STG * 4, tid);
        cp_commit();
    }

    int sc = 0;
    int sw = STAGES - 1;
    const float* Akt = A + (STAGES - 1) * BKK;
    const float* Bkt = Bm + (size_t)(STAGES - 1) * BKK * NDIM;

    for (int i = 0; i < nch; i++) {
        cp_wait<STAGES - 2>();
        __syncthreads();
        const uint32_t* sAc = (const uint32_t*)(sA + sc * A_STG);
        const float* sBc = sB + sc * B_STG;
        const bool doio = (i + STAGES - 1) < nch;
        const uint32_t wAu = sAu + sw * A_STG * 4;
        const uint32_t wBu = sBu + sw * B_STG * 4;

        #pragma unroll
        for (int kk = 0; kk < 4; kk++) {
            const int k0 = kk * 8;
            uint32_t af[4][4];
            #pragma unroll
            for (int mi = 0; mi < 4; mi++) {
                const uint32_t* ap = sAc + (wm*64 + mi*16 + gid) * PA + k0 + tig;
                af[mi][0] = ap[0];
                af[mi][1] = ap[8 * PA];
                af[mi][2] = ap[4];
                af[mi][3] = ap[8 * PA + 4];
            }
            uint32_t bf[8][2];
            #pragma unroll
            for (int ni = 0; ni < 8; ni++) {
                const float* bp = sBc + (k0 + tig) * PB + wn*64 + ni*8 + gid;
                bf[ni][0] = f2tf32(bp[0]);
                bf[ni][1] = f2tf32(bp[4 * PB]);
            }
            if (doio) {
                #pragma unroll
                for (int q = kk * 2; q < kk * 2 + 2; q++) {
                    int idx = q * GT + tid;
                    int row = idx >> 3;
                    int c4 = idx & 7;
                    cp16(wAu + (row * PA + c4 * 4) * 4,
                         Akt + (size_t)(bm0 + row) * KDIM + c4 * 4);
                }
                #pragma unroll
                for (int q = kk * 2; q < kk * 2 + 2; q++) {
                    int idx = q * GT + tid;
                    int row = idx >> 5;
                    int c4 = idx & 31;
                    cp16(wBu + (row * PB + c4 * 4) * 4,
                         Bkt + (size_t)row * NDIM + bn0 + c4 * 4);
                }
            }
            #pragma unroll
            for (int mi = 0; mi < 4; mi++)
                #pragma unroll
                for (int ni = 0; ni < 8; ni++)
                    asm volatile(
                        "mma.sync.aligned.m16n8k8.row.col.f32.tf32.tf32.f32 "
                        "{%0,%1,%2,%3}, {%4,%5,%6,%7}, {%8,%9}, {%0,%1,%2,%3};\n"
                        : "+f"(acc[mi][ni][0]), "+f"(acc[mi][ni][1]),
                          "+f"(acc[mi][ni][2]), "+f"(acc[mi][ni][3])
                        : "r"(af[mi][0]), "r"(af[mi][1]), "r"(af[mi][2]), "r"(af[mi][3]),
                          "r"(bf[ni][0]), "r"(bf[ni][1]));
        }
        cp_commit();
        sc = (sc + 1 == STAGES) ? 0 : sc + 1;
        sw = (sw + 1 == STAGES) ? 0 : sw + 1;
        Akt += BKK;
        Bkt += (size_t)BKK * NDIM;
    }
}

// GEMM1: g_hidden = round_tf32(gelu(g_fin @ W1 + b1));  M=4096, N=8192, K=2048
__global__ __launch_bounds__(GT, 2) void gemm1_kernel(
    const float* __restrict__ W1, const float* __restrict__ b1)
{
    extern __shared__ float sm[];
    float acc[4][8][4];
    #pragma unroll
    for (int i = 0; i < 4; i++)
        #pragma unroll
        for (int j = 0; j < 8; j++)
            #pragma unroll
            for (int k = 0; k < 4; k++) acc[i][j][k] = 0.0f;

    const int bm0 = blockIdx.y * GBM;
    const int bn0 = blockIdx.x * GBN;
    gemm_mainloop(g_fin, W1, CD, DFF, bm0, bn0, sm, acc);

    const int tid = threadIdx.x;
    const int lane = tid & 31, wid = tid >> 5;
    const int wm = wid >> 1, wn = wid & 1;
    const int gid = lane >> 2, tig = lane & 3;

    #pragma unroll
    for (int mi = 0; mi < 4; mi++) {
        int r0 = bm0 + wm*64 + mi*16 + gid;
        #pragma unroll
        for (int ni = 0; ni < 8; ni++) {
            int c = bn0 + wn*64 + ni*8 + tig*2;
            float2 bv = *(const float2*)(b1 + c);
            float2 v0, v1;
            v0.x = roundtf(gelu_tanh(acc[mi][ni][0] + bv.x));
            v0.y = roundtf(gelu_tanh(acc[mi][ni][1] + bv.y));
            v1.x = roundtf(gelu_tanh(acc[mi][ni][2] + bv.x));
            v1.y = roundtf(gelu_tanh(acc[mi][ni][3] + bv.y));
            *(float2*)(g_hidden + (size_t)r0 * DFF + c) = v0;
            *(float2*)(g_hidden + (size_t)(r0 + 8) * DFF + c) = v1;
        }
    }
}

__device__ __forceinline__ void epi2_row(float* __restrict__ out, int r, int c,
                                         float f0, float f1, float4 hp) {
    float hv[4] = {hp.x, hp.y, hp.z, hp.w};
    #pragma unroll
    for (int m = 0; m < 4; m++) {
        float2* p = (float2*)(out + ((size_t)r * 4 + m) * CD + c);
        float2 o = *p;
        o.x = fmaf(hv[m], f0, o.x);
        o.y = fmaf(hv[m], f1, o.y);
        *p = o;
    }
}

// GEMM2: out[b,m,:] += hpost[b,m]*(g_hidden @ W2 + b2);  M=4096, N=2048, K=8192
__global__ __launch_bounds__(GT, 2) void gemm2_kernel(
    const float* __restrict__ W2, const float* __restrict__ b2,
    float* __restrict__ out)
{
    extern __shared__ float sm[];
    float acc[4][8][4];
    #pragma unroll
    for (int i = 0; i < 4; i++)
        #pragma unroll
        for (int j = 0; j < 8; j++)
            #pragma unroll
            for (int k = 0; k < 4; k++) acc[i][j][k] = 0.0f;

    const int bm0 = blockIdx.y * GBM;
    const int bn0 = blockIdx.x * GBN;
    gemm_mainloop(g_hidden, W2, DFF, CD, bm0, bn0, sm, acc);

    const int tid = threadIdx.x;
    const int lane = tid & 31, wid = tid >> 5;
    const int wm = wid >> 1, wn = wid & 1;
    const int gid = lane >> 2, tig = lane & 3;

    #pragma unroll
    for (int mi = 0; mi < 4; mi++) {
        int r0 = bm0 + wm*64 + mi*16 + gid;
        int r1 = r0 + 8;
        float4 hp0 = *(const float4*)(g_hpost + r0 * 4);
        float4 hp1 = *(const float4*)(g_hpost + r1 * 4);
        #pragma unroll
        for (int ni = 0; ni < 8; ni++) {
            int c = bn0 + wn*64 + ni*8 + tig*2;
            float2 bv = *(const float2*)(b2 + c);
            epi2_row(out, r0, c, acc[mi][ni][0] + bv.x, acc[mi][ni][1] + bv.y, hp0);
            epi2_row(out, r1, c, acc[mi][ni][2] + bv.x, acc[mi][ni][3] + bv.y, hp1);
        }
    }
}

// ---------------------------------------------------------------- launch
extern "C" void kernel_launch(void* const* d_in, const int* in_sizes, int n_in,
                              void* d_out, int out_size) {
    (void)in_sizes; (void)n_in; (void)out_size;
    const float* x         = (const float*)d_in[0];
    const float* phi_pre   = (const float*)d_in[1];
    const float* phi_post  = (const float*)d_in[2];
    const float* phi_res   = (const float*)d_in[3];
    const float* bias_pre  = (const float*)d_in[4];
    const float* bias_post = (const float*)d_in[5];
    const float* bias_res  = (const float*)d_in[6];
    const float* alpha_pre = (const float*)d_in[7];
    const float* alpha_post= (const float*)d_in[8];
    const float* alpha_res = (const float*)d_in[9];
    const float* W1        = (const float*)d_in[10];
    const float* b1        = (const float*)d_in[11];
    const float* W2        = (const float*)d_in[12];
    const float* b2        = (const float*)d_in[13];
    float* out = (float*)d_out;

    static bool configured = false;
    if (!configured) {
        cudaFuncSetAttribute(gemm1_kernel, cudaFuncAttributeMaxDynamicSharedMemorySize, SMEM_GEMM);
        cudaFuncSetAttribute(gemm2_kernel, cudaFuncAttributeMaxDynamicSharedMemorySize, SMEM_GEMM);
        configured = true;
    }

    dots_kernel<<<BR / DROWS, 128>>>(x, phi_pre, phi_post, phi_res,
                                     bias_pre, bias_post, bias_res,
                                     alpha_pre, alpha_post, alpha_res);
    apply_kernel<<<BR, 256>>>(x, out);

    gemm1_kernel<<<dim3(DFF / GBN, BR / GBM), GT, SMEM_GEMM>>>(W1, b1);
    gemm2_kernel<<<dim3(CD / GBN, BR / GBM), GT, SMEM_GEMM>>>(W2, b2, out);
}

// round 15
// speedup vs baseline: 1.0185x; 1.0185x over previous
#include <cuda_runtime.h>
#include <cstdint>

#define NS 4
#define CD 2048
#define FLT 8192
#define BR 4096
#define DFF 8192

// ---------------------------------------------------------------- scratch
__device__ float g_fin[(size_t)BR * CD];        // (B, C)    32 MB  (tf32-rounded)
__device__ float g_hidden[(size_t)BR * DFF];    // (B, DFF) 128 MB  (tf32-rounded)
__device__ float g_hpost[BR * NS];              // (B, 4)
__device__ float g_w1r[(size_t)CD * DFF];       // W1 rounded  64 MB
__device__ float g_w2r[(size_t)DFF * CD];       // W2 rounded  64 MB

// ---------------------------------------------------------------- helpers
__device__ __forceinline__ float fast_tanhf(float u) {
    float e = __expf(2.0f * u);
    return 1.0f - __fdividef(2.0f, e + 1.0f);
}
__device__ __forceinline__ float gelu_tanh(float x) {
    float u = 0.7978845608028654f * fmaf(0.044715f * x, x * x, x);
    return 0.5f * x * (1.0f + fast_tanhf(u));
}
__device__ __forceinline__ uint32_t f2tf32(float x) {
    uint32_t u;
    asm("cvt.rna.tf32.f32 %0, %1;" : "=r"(u) : "f"(x));
    return u;
}
__device__ __forceinline__ float roundtf(float x) { return __uint_as_float(f2tf32(x)); }
__device__ __forceinline__ uint32_t smem_u32(const void* p) {
    uint32_t a;
    asm("{ .reg .u64 t; cvta.to.shared.u64 t, %1; cvt.u32.u64 %0, t; }" : "=r"(a) : "l"(p));
    return a;
}
__device__ __forceinline__ void cp16(uint32_t dst, const void* src) {
    asm volatile("cp.async.cg.shared.global [%0], [%1], 16;" :: "r"(dst), "l"(src));
}
__device__ __forceinline__ void cp_commit() {
    asm volatile("cp.async.commit_group;" ::: "memory");
}
template <int N>
__device__ __forceinline__ void cp_wait() {
    asm volatile("cp.async.wait_group %0;" :: "n"(N) : "memory");
}

// ---------------------------------------------------------------- weight prep (tf32 round)
__global__ __launch_bounds__(256) void round_both_kernel(
    const float* __restrict__ w1, float* __restrict__ w1d,
    const float* __restrict__ w2, float* __restrict__ w2d, int n4each)
{
    int i = blockIdx.x * 256 + threadIdx.x;
    const float4* src;
    float4* dst;
    int j;
    if (i < n4each) { src = (const float4*)w1; dst = (float4*)w1d; j = i; }
    else            { src = (const float4*)w2; dst = (float4*)w2d; j = i - n4each; }
    float4 v = src[j];
    v.x = roundtf(v.x); v.y = roundtf(v.y);
    v.z = roundtf(v.z); v.w = roundtf(v.w);
    dst[j] = v;
}

// ---------------------------------------------------------------- gates fused (dots + sinkhorn + apply)
// 4 rows/block, 128 threads, 3 CTAs/SM. Phase 1: 25 dots/row streaming x+phi.
// Phase 2 (tid<4): sigmoids + sinkhorn -> smem. Phase 3: fin + residual writes
// (x re-read; L2-hot from phase 1).
#define DROWS 4
__global__ __launch_bounds__(128, 3) void gates_kernel(
    const float* __restrict__ x,
    const float* __restrict__ phi_pre,
    const float* __restrict__ phi_post,
    const float* __restrict__ phi_res,
    const float* __restrict__ bias_pre,
    const float* __restrict__ bias_post,
    const float* __restrict__ bias_res,
    const float* __restrict__ alpha_pre_p,
    const float* __restrict__ alpha_post_p,
    const float* __restrict__ alpha_res_p,
    float* __restrict__ out)
{
    __shared__ float sred[4][DROWS * 25];
    __shared__ float sdot[DROWS * 25];
    __shared__ float spre[DROWS][4];
    __shared__ float sres[DROWS][16];

    const int tid = threadIdx.x;
    const int b0 = blockIdx.x * DROWS;
    const float* xb = x + (size_t)b0 * FLT;

    float acc[DROWS * 25];
    #pragma unroll
    for (int j = 0; j < DROWS * 25; j++) acc[j] = 0.0f;

    const float4* pp4 = (const float4*)phi_pre;
    const float4* pq4 = (const float4*)phi_post;
    const float4* pr4 = (const float4*)phi_res;

    #pragma unroll 2
    for (int it = 0; it < FLT / 128; it++) {
        const int f = tid + it * 128;
        float xv[DROWS];
        #pragma unroll
        for (int r = 0; r < DROWS; r++) {
            xv[r] = xb[r * FLT + f];
            acc[r * 25 + 24] = fmaf(xv[r], xv[r], acc[r * 25 + 24]);
        }
        float4 p = pp4[f];
        #pragma unroll
        for (int r = 0; r < DROWS; r++) {
            acc[r*25 + 0] = fmaf(xv[r], p.x, acc[r*25 + 0]);
            acc[r*25 + 1] = fmaf(xv[r], p.y, acc[r*25 + 1]);
            acc[r*25 + 2] = fmaf(xv[r], p.z, acc[r*25 + 2]);
            acc[r*25 + 3] = fmaf(xv[r], p.w, acc[r*25 + 3]);
        }
        float4 q = pq4[f];
        #pragma unroll
        for (int r = 0; r < DROWS; r++) {
            acc[r*25 + 4] = fmaf(xv[r], q.x, acc[r*25 + 4]);
            acc[r*25 + 5] = fmaf(xv[r], q.y, acc[r*25 + 5]);
            acc[r*25 + 6] = fmaf(xv[r], q.z, acc[r*25 + 6]);
            acc[r*25 + 7] = fmaf(xv[r], q.w, acc[r*25 + 7]);
        }
        #pragma unroll
        for (int g = 0; g < 4; g++) {
            float4 rr = pr4[f * 4 + g];
            #pragma unroll
            for (int r = 0; r < DROWS; r++) {
                acc[r*25 + 8 + g*4 + 0] = fmaf(xv[r], rr.x, acc[r*25 + 8 + g*4 + 0]);
                acc[r*25 + 8 + g*4 + 1] = fmaf(xv[r], rr.y, acc[r*25 + 8 + g*4 + 1]);
                acc[r*25 + 8 + g*4 + 2] = fmaf(xv[r], rr.z, acc[r*25 + 8 + g*4 + 2]);
                acc[r*25 + 8 + g*4 + 3] = fmaf(xv[r], rr.w, acc[r*25 + 8 + g*4 + 3]);
            }
        }
    }

    const int lane = tid & 31, warp = tid >> 5;
    #pragma unroll
    for (int j = 0; j < DROWS * 25; j++) {
        float v = acc[j];
        v += __shfl_xor_sync(0xffffffffu, v, 16);
        v += __shfl_xor_sync(0xffffffffu, v, 8);
        v += __shfl_xor_sync(0xffffffffu, v, 4);
        v += __shfl_xor_sync(0xffffffffu, v, 2);
        v += __shfl_xor_sync(0xffffffffu, v, 1);
        if (lane == 0) sred[warp][j] = v;
    }
    __syncthreads();
    if (tid < DROWS * 25) {
        sdot[tid] = sred[0][tid] + sred[1][tid] + sred[2][tid] + sred[3][tid];
    }
    __syncthreads();
    if (tid < DROWS) {
        const int rowoff = tid * 25;
        const int b = b0 + tid;
        float inv_rms = rsqrtf(sdot[rowoff + 24] * (1.0f / (float)FLT) + 1e-8f);
        float a_pre = alpha_pre_p[0], a_post = alpha_post_p[0], a_res = alpha_res_p[0];
        #pragma unroll
        for (int n = 0; n < 4; n++) {
            float tpre = fmaf(a_pre, sdot[rowoff + n] * inv_rms, bias_pre[n]);
            spre[tid][n] = 1.0f / (1.0f + expf(-tpre));
            float tpost = fmaf(a_post, sdot[rowoff + 4 + n] * inv_rms, bias_post[n]);
            g_hpost[b * 4 + n] = 2.0f / (1.0f + expf(-tpost));
        }
        float M[4][4];
        #pragma unroll
        for (int m = 0; m < 4; m++)
            #pragma unroll
            for (int n = 0; n < 4; n++)
                M[m][n] = expf(fmaf(a_res, sdot[rowoff + 8 + m*4 + n] * inv_rms, bias_res[m*4 + n]));
        #pragma unroll 1
        for (int it = 0; it < 20; it++) {
            #pragma unroll
            for (int m = 0; m < 4; m++) {
                float rs = M[m][0] + M[m][1] + M[m][2] + M[m][3] + 1e-12f;
                float inv = 1.0f / rs;
                M[m][0] *= inv; M[m][1] *= inv; M[m][2] *= inv; M[m][3] *= inv;
            }
            #pragma unroll
            for (int n = 0; n < 4; n++) {
                float cs = M[0][n] + M[1][n] + M[2][n] + M[3][n] + 1e-12f;
                float inv = 1.0f / cs;
                M[0][n] *= inv; M[1][n] *= inv; M[2][n] *= inv; M[3][n] *= inv;
            }
        }
        #pragma unroll
        for (int m = 0; m < 4; m++)
            #pragma unroll
            for (int n = 0; n < 4; n++)
                sres[tid][m * 4 + n] = M[m][n];
    }
    __syncthreads();

    // Phase 3: fin + residual writes for the block's 4 rows (x re-read, L2-hot)
    #pragma unroll 1
    for (int r = 0; r < DROWS; r++) {
        const int b = b0 + r;
        const float h0 = spre[r][0], h1 = spre[r][1], h2 = spre[r][2], h3 = spre[r][3];
        float R[4][4];
        #pragma unroll
        for (int m = 0; m < 4; m++)
            #pragma unroll
            for (int n = 0; n < 4; n++)
                R[m][n] = sres[r][m * 4 + n];

        const float4* xr4 = (const float4*)(x + (size_t)b * FLT);
        float4* fin4 = (float4*)(g_fin + (size_t)b * CD);
        #pragma unroll 1
        for (int c = tid; c < CD / 4; c += 128) {
            float4 x0 = xr4[c];
            float4 x1 = xr4[512 + c];
            float4 x2 = xr4[1024 + c];
            float4 x3 = xr4[1536 + c];
            float4 fv;
            fv.x = roundtf(h0*x0.x + h1*x1.x + h2*x2.x + h3*x3.x);
            fv.y = roundtf(h0*x0.y + h1*x1.y + h2*x2.y + h3*x3.y);
            fv.z = roundtf(h0*x0.z + h1*x1.z + h2*x2.z + h3*x3.z);
            fv.w = roundtf(h0*x0.w + h1*x1.w + h2*x2.w + h3*x3.w);
            fin4[c] = fv;
            #pragma unroll
            for (int m = 0; m < 4; m++) {
                float4 ov;
                ov.x = R[m][0]*x0.x + R[m][1]*x1.x + R[m][2]*x2.x + R[m][3]*x3.x;
                ov.y = R[m][0]*x0.y + R[m][1]*x1.y + R[m][2]*x2.y + R[m][3]*x3.y;
                ov.z = R[m][0]*x0.z + R[m][1]*x1.z + R[m][2]*x2.z + R[m][3]*x3.z;
                ov.w = R[m][0]*x0.w + R[m][1]*x1.w + R[m][2]*x2.w + R[m][3]*x3.w;
                ((float4*)(out + ((size_t)b * 4 + m) * CD))[c] = ov;
            }
        }
    }
}

// ---------------------------------------------------------------- tf32 GEMM  [R11 structure]
#define STAGES 3
#define BKK 32
#define GBM 128
#define GBN 128
#define GT 128
#define PA 36
#define PB 136
#define A_STG (GBM * PA)
#define B_STG (BKK * PB)
#define SMEM_GEMM ((STAGES * (A_STG + B_STG)) * 4)   // 107520 B

__device__ __forceinline__ void issue_chunk(
    const float* __restrict__ A, const float* __restrict__ Bm,
    int KDIM, int NDIM, int bm0, int bn0, int kt,
    uint32_t smA, uint32_t smB, int tid)
{
    #pragma unroll
    for (int q = 0; q < 8; q++) {
        int idx = q * GT + tid;
        int row = idx >> 3;
        int c4 = idx & 7;
        cp16(smA + (row * PA + c4 * 4) * 4,
             A + (size_t)(bm0 + row) * KDIM + kt + c4 * 4);
    }
    #pragma unroll
    for (int q = 0; q < 8; q++) {
        int idx = q * GT + tid;
        int row = idx >> 5;
        int c4 = idx & 31;
        cp16(smB + (row * PB + c4 * 4) * 4,
             Bm + (size_t)(kt + row) * NDIM + bn0 + c4 * 4);
    }
}

__device__ __forceinline__ void gemm_mainloop(
    const float* __restrict__ A, const float* __restrict__ Bm,
    int KDIM, int NDIM, int bm0, int bn0,
    float* sm, float acc[4][8][4])
{
    const int tid = threadIdx.x;
    const int lane = tid & 31, wid = tid >> 5;
    const int wm = wid >> 1, wn = wid & 1;
    const int gid = lane >> 2, tig = lane & 3;

    float* sA = sm;
    float* sB = sm + STAGES * A_STG;
    const uint32_t sAu = smem_u32(sA);
    const uint32_t sBu = smem_u32(sB);

    const int nch = KDIM / BKK;

    #pragma unroll
    for (int i = 0; i < STAGES - 1; i++) {
        issue_chunk(A, Bm, KDIM, NDIM, bm0, bn0, i * BKK,
                    sAu + i * A_STG * 4, sBu + i * B_STG * 4, tid);
        cp_commit();
    }

    int sc = 0;
    int sw = STAGES - 1;
    const float* Akt = A + (STAGES - 1) * BKK;
    const float* Bkt = Bm + (size_t)(STAGES - 1) * BKK * NDIM;

    for (int i = 0; i < nch; i++) {
        cp_wait<STAGES - 2>();
        __syncthreads();
        const uint32_t* sAc = (const uint32_t*)(sA + sc * A_STG);
        const uint32_t* sBc = (const uint32_t*)(sB + sc * B_STG);
        const bool doio = (i + STAGES - 1) < nch;
        const uint32_t wAu = sAu + sw * A_STG * 4;
        const uint32_t wBu = sBu + sw * B_STG * 4;

        #pragma unroll
        for (int kk = 0; kk < 4; kk++) {
            const int k0 = kk * 8;
            uint32_t af[4][4];
            #pragma unroll
            for (int mi = 0; mi < 4; mi++) {
                const uint32_t* ap = sAc + (wm*64 + mi*16 + gid) * PA + k0 + tig;
                af[mi][0] = ap[0];
                af[mi][1] = ap[8 * PA];
                af[mi][2] = ap[4];
                af[mi][3] = ap[8 * PA + 4];
            }
            uint32_t bf[8][2];
            #pragma unroll
            for (int ni = 0; ni < 8; ni++) {
                const uint32_t* bp = sBc + (k0 + tig) * PB + wn*64 + ni*8 + gid;
                bf[ni][0] = bp[0];
                bf[ni][1] = bp[4 * PB];
            }
            if (doio) {
                #pragma unroll
                for (int q = kk * 2; q < kk * 2 + 2; q++) {
                    int idx = q * GT + tid;
                    int row = idx >> 3;
                    int c4 = idx & 7;
                    cp16(wAu + (row * PA + c4 * 4) * 4,
                         Akt + (size_t)(bm0 + row) * KDIM + c4 * 4);
                }
                #pragma unroll
                for (int q = kk * 2; q < kk * 2 + 2; q++) {
                    int idx = q * GT + tid;
                    int row = idx >> 5;
                    int c4 = idx & 31;
                    cp16(wBu + (row * PB + c4 * 4) * 4,
                         Bkt + (size_t)row * NDIM + bn0 + c4 * 4);
                }
            }
            #pragma unroll
            for (int mi = 0; mi < 4; mi++)
                #pragma unroll
                for (int ni = 0; ni < 8; ni++)
                    asm volatile(
                        "mma.sync.aligned.m16n8k8.row.col.f32.tf32.tf32.f32 "
                        "{%0,%1,%2,%3}, {%4,%5,%6,%7}, {%8,%9}, {%0,%1,%2,%3};\n"
                        : "+f"(acc[mi][ni][0]), "+f"(acc[mi][ni][1]),
                          "+f"(acc[mi][ni][2]), "+f"(acc[mi][ni][3])
                        : "r"(af[mi][0]), "r"(af[mi][1]), "r"(af[mi][2]), "r"(af[mi][3]),
                          "r"(bf[ni][0]), "r"(bf[ni][1]));
        }
        cp_commit();
        sc = (sc + 1 == STAGES) ? 0 : sc + 1;
        sw = (sw + 1 == STAGES) ? 0 : sw + 1;
        Akt += BKK;
        Bkt += (size_t)BKK * NDIM;
    }
}

// GEMM1: g_hidden = round_tf32(gelu(g_fin @ W1r + b1));  M=4096, N=8192, K=2048
__global__ __launch_bounds__(GT, 2) void gemm1_kernel(const float* __restrict__ b1)
{
    extern __shared__ float sm[];
    float acc[4][8][4];
    #pragma unroll
    for (int i = 0; i < 4; i++)
        #pragma unroll
        for (int j = 0; j < 8; j++)
            #pragma unroll
            for (int k = 0; k < 4; k++) acc[i][j][k] = 0.0f;

    const int bm0 = blockIdx.y * GBM;
    const int bn0 = blockIdx.x * GBN;
    gemm_mainloop(g_fin, g_w1r, CD, DFF, bm0, bn0, sm, acc);

    const int tid = threadIdx.x;
    const int lane = tid & 31, wid = tid >> 5;
    const int wm = wid >> 1, wn = wid & 1;
    const int gid = lane >> 2, tig = lane & 3;

    #pragma unroll
    for (int mi = 0; mi < 4; mi++) {
        int r0 = bm0 + wm*64 + mi*16 + gid;
        #pragma unroll
        for (int ni = 0; ni < 8; ni++) {
            int c = bn0 + wn*64 + ni*8 + tig*2;
            float2 bv = *(const float2*)(b1 + c);
            float2 v0, v1;
            v0.x = roundtf(gelu_tanh(acc[mi][ni][0] + bv.x));
            v0.y = roundtf(gelu_tanh(acc[mi][ni][1] + bv.y));
            v1.x = roundtf(gelu_tanh(acc[mi][ni][2] + bv.x));
            v1.y = roundtf(gelu_tanh(acc[mi][ni][3] + bv.y));
            *(float2*)(g_hidden + (size_t)r0 * DFF + c) = v0;
            *(float2*)(g_hidden + (size_t)(r0 + 8) * DFF + c) = v1;
        }
    }
}

__device__ __forceinline__ void epi2_row(float* __restrict__ out, int r, int c,
                                         float f0, float f1, float4 hp) {
    float hv[4] = {hp.x, hp.y, hp.z, hp.w};
    #pragma unroll
    for (int m = 0; m < 4; m++) {
        float2* p = (float2*)(out + ((size_t)r * 4 + m) * CD + c);
        float2 o = *p;
        o.x = fmaf(hv[m], f0, o.x);
        o.y = fmaf(hv[m], f1, o.y);
        *p = o;
    }
}

// GEMM2: out[b,m,:] += hpost[b,m]*(g_hidden @ W2r + b2);  M=4096, N=2048, K=8192
__global__ __launch_bounds__(GT, 2) void gemm2_kernel(
    const float* __restrict__ b2, float* __restrict__ out)
{
    extern __shared__ float sm[];
    float acc[4][8][4];
    #pragma unroll
    for (int i = 0; i < 4; i++)
        #pragma unroll
        for (int j = 0; j < 8; j++)
            #pragma unroll
            for (int k = 0; k < 4; k++) acc[i][j][k] = 0.0f;

    const int bm0 = blockIdx.y * GBM;
    const int bn0 = blockIdx.x * GBN;
    gemm_mainloop(g_hidden, g_w2r, DFF, CD, bm0, bn0, sm, acc);

    const int tid = threadIdx.x;
    const int lane = tid & 31, wid = tid >> 5;
    const int wm = wid >> 1, wn = wid & 1;
    const int gid = lane >> 2, tig = lane & 3;

    #pragma unroll
    for (int mi = 0; mi < 4; mi++) {
        int r0 = bm0 + wm*64 + mi*16 + gid;
        int r1 = r0 + 8;
        float4 hp0 = *(const float4*)(g_hpost + r0 * 4);
        float4 hp1 = *(const float4*)(g_hpost + r1 * 4);
        #pragma unroll
        for (int ni = 0; ni < 8; ni++) {
            int c = bn0 + wn*64 + ni*8 + tig*2;
            float2 bv = *(const float2*)(b2 + c);
            epi2_row(out, r0, c, acc[mi][ni][0] + bv.x, acc[mi][ni][1] + bv.y, hp0);
            epi2_row(out, r1, c, acc[mi][ni][2] + bv.x, acc[mi][ni][3] + bv.y, hp1);
        }
    }
}

// ---------------------------------------------------------------- launch
extern "C" void kernel_launch(void* const* d_in, const int* in_sizes, int n_in,
                              void* d_out, int out_size) {
    (void)in_sizes; (void)n_in; (void)out_size;
    const float* x         = (const float*)d_in[0];
    const float* phi_pre   = (const float*)d_in[1];
    const float* phi_post  = (const float*)d_in[2];
    const float* phi_res   = (const float*)d_in[3];
    const float* bias_pre  = (const float*)d_in[4];
    const float* bias_post = (const float*)d_in[5];
    const float* bias_res  = (const float*)d_in[6];
    const float* alpha_pre = (const float*)d_in[7];
    const float* alpha_post= (const float*)d_in[8];
    const float* alpha_res = (const float*)d_in[9];
    const float* W1        = (const float*)d_in[10];
    const float* b1        = (const float*)d_in[11];
    const float* W2        = (const float*)d_in[12];
    const float* b2        = (const float*)d_in[13];
    float* out = (float*)d_out;

    static float* w1r_ptr = nullptr;
    static float* w2r_ptr = nullptr;
    if (!w1r_ptr) {
        cudaGetSymbolAddress((void**)&w1r_ptr, g_w1r);
        cudaGetSymbolAddress((void**)&w2r_ptr, g_w2r);
        cudaFuncSetAttribute(gemm1_kernel, cudaFuncAttributeMaxDynamicSharedMemorySize, SMEM_GEMM);
        cudaFuncSetAttribute(gemm2_kernel, cudaFuncAttributeMaxDynamicSharedMemorySize, SMEM_GEMM);
    }

    const int n4each = (CD * DFF) / 4;
    round_both_kernel<<<(2 * n4each + 255) / 256, 256>>>(W1, w1r_ptr, W2, w2r_ptr, n4each);

    gates_kernel<<<BR / DROWS, 128>>>(x, phi_pre, phi_post, phi_res,
                                      bias_pre, bias_post, bias_res,
                                      alpha_pre, alpha_post, alpha_res, out);

    gemm1_kernel<<<dim3(DFF / GBN, BR / GBM), GT, SMEM_GEMM>>>(b1);
    gemm2_kernel<<<dim3(CD / GBN, BR / GBM), GT, SMEM_GEMM>>>(b2, out);
}